// round 3
// baseline (speedup 1.0000x reference)
#include <cuda_runtime.h>
#include <cuda_bf16.h>
#include <math.h>

// ---------------- problem constants ----------------
#define B_   8
#define H_   32
#define W_   32
#define L_   1024
#define C_   512
#define DI_  1024
#define K_   4
#define N_   16
#define R_   32
#define ML_  (B_ * L_)          // 8192 rows

// ---------------- scratch (device globals, zero-init bss) ----------------
__device__ float g_xn  [(size_t)ML_ * C_];            // layernorm(x)           16 MB
__device__ float g_xz  [(size_t)ML_ * 2 * DI_];       // in_proj output         64 MB
__device__ float g_xc  [(size_t)ML_ * DI_];           // conv+silu, (b,l,d)     32 MB
__device__ float g_xdbl[(size_t)B_ * K_ * L_ * 64];   // (bk, t, c)              8 MB
__device__ float g_dts [(size_t)B_ * K_ * L_ * DI_];  // (bk, t, d)            128 MB
__device__ float g_ys  [(size_t)B_ * K_ * L_ * DI_];  // (bk, l_spatial, d)    128 MB
__device__ float g_yf  [(size_t)ML_ * DI_];           // pre-out_proj           32 MB

// scan index map: spatial l for direction k at scan step t
__device__ __forceinline__ int map_t(int k, int t) {
    int tt = (k & 2) ? (L_ - 1 - t) : t;
    return (k & 1) ? (((tt & 31) << 5) | (tt >> 5)) : tt;
}

// ---------------- input layernorm (row = 512) ----------------
__global__ void __launch_bounds__(128) ln_kernel(const float* __restrict__ x,
                                                 const float* __restrict__ w,
                                                 const float* __restrict__ bb) {
    int bl = blockIdx.x;
    int tid = threadIdx.x;
    const float* xr = x + (size_t)bl * C_;
    float4 v = *(const float4*)(xr + tid * 4);
    float s = v.x + v.y + v.z + v.w;
    float q = v.x * v.x + v.y * v.y + v.z * v.z + v.w * v.w;
#pragma unroll
    for (int o = 16; o; o >>= 1) {
        s += __shfl_xor_sync(0xffffffffu, s, o);
        q += __shfl_xor_sync(0xffffffffu, q, o);
    }
    __shared__ float shs[4], shq[4];
    if ((tid & 31) == 0) { shs[tid >> 5] = s; shq[tid >> 5] = q; }
    __syncthreads();
    float S = shs[0] + shs[1] + shs[2] + shs[3];
    float Q = shq[0] + shq[1] + shq[2] + shq[3];
    float mu  = S * (1.0f / C_);
    float var = Q * (1.0f / C_) - mu * mu;
    float rs  = rsqrtf(var + 1e-5f);
    float4 wv = *(const float4*)(w + tid * 4);
    float4 bv = *(const float4*)(bb + tid * 4);
    float4 o;
    o.x = (v.x - mu) * rs * wv.x + bv.x;
    o.y = (v.y - mu) * rs * wv.y + bv.y;
    o.z = (v.z - mu) * rs * wv.z + bv.z;
    o.w = (v.w - mu) * rs * wv.w + bv.w;
    *(float4*)(g_xn + (size_t)bl * C_ + tid * 4) = o;
}

// ---------------- generic NT sgemm: C[M,N] = A[M,K] * W[N,K]^T ----------------
// MODE 0: A=g_xn (K=512), C=g_xz (N=2048).  MODE 1: A=g_yf (K=1024), C=out+resid (N=512).
template <int MODE>
__global__ void __launch_bounds__(256) sgemm_nt(const float* __restrict__ Wm,
                                                const float* __restrict__ resid,
                                                float* __restrict__ Cout) {
    constexpr int Kd = (MODE == 0) ? C_ : DI_;
    constexpr int Nd = (MODE == 0) ? 2 * DI_ : C_;
    const float* A = (MODE == 0) ? g_xn : g_yf;
    float* C = (MODE == 0) ? g_xz : Cout;

    __shared__ float As[16][132];
    __shared__ float Bs[16][132];
    int tid = threadIdx.x;
    int tx = tid & 15, ty = tid >> 4;
    int m0 = blockIdx.y * 128, n0 = blockIdx.x * 128;
    float acc[8][8];
#pragma unroll
    for (int i = 0; i < 8; ++i)
#pragma unroll
        for (int j = 0; j < 8; ++j) acc[i][j] = 0.0f;

    for (int k0 = 0; k0 < Kd; k0 += 16) {
#pragma unroll
        for (int it = 0; it < 2; ++it) {
            int t4 = tid + it * 256;
            int row = t4 >> 2;
            int kc = (t4 & 3) << 2;
            float4 va = *(const float4*)(A + (size_t)(m0 + row) * Kd + (k0 + kc));
            As[kc + 0][row] = va.x; As[kc + 1][row] = va.y;
            As[kc + 2][row] = va.z; As[kc + 3][row] = va.w;
            float4 vb = *(const float4*)(Wm + (size_t)(n0 + row) * Kd + (k0 + kc));
            Bs[kc + 0][row] = vb.x; Bs[kc + 1][row] = vb.y;
            Bs[kc + 2][row] = vb.z; Bs[kc + 3][row] = vb.w;
        }
        __syncthreads();
#pragma unroll
        for (int kk = 0; kk < 16; ++kk) {
            float a[8], b[8];
            *(float4*)&a[0] = *(const float4*)&As[kk][ty * 8];
            *(float4*)&a[4] = *(const float4*)&As[kk][ty * 8 + 4];
            *(float4*)&b[0] = *(const float4*)&Bs[kk][tx * 8];
            *(float4*)&b[4] = *(const float4*)&Bs[kk][tx * 8 + 4];
#pragma unroll
            for (int i = 0; i < 8; ++i)
#pragma unroll
                for (int j = 0; j < 8; ++j)
                    acc[i][j] = fmaf(a[i], b[j], acc[i][j]);
        }
        __syncthreads();
    }
#pragma unroll
    for (int i = 0; i < 8; ++i) {
        size_t ro = (size_t)(m0 + ty * 8 + i) * Nd + n0 + tx * 8;
#pragma unroll
        for (int jj = 0; jj < 8; jj += 4) {
            float4 v;
            v.x = acc[i][jj + 0]; v.y = acc[i][jj + 1];
            v.z = acc[i][jj + 2]; v.w = acc[i][jj + 3];
            if (MODE == 1) {
                float4 r = *(const float4*)(resid + ro + jj);
                v.x += r.x; v.y += r.y; v.z += r.z; v.w += r.w;
            }
            *(float4*)(C + ro + jj) = v;
        }
    }
}

// ---------------- depthwise 3x3 conv + bias + silu ----------------
// in: g_xz cols [0, DI), layout (b, l, 2*DI).  out: g_xc (b, l, d)
__global__ void __launch_bounds__(256) conv_kernel(const float* __restrict__ cw,
                                                   const float* __restrict__ cb) {
    int l = blockIdx.x, b = blockIdx.y;
    int h = l >> 5, w = l & 31;
    int tid = threadIdx.x;
#pragma unroll
    for (int i = 0; i < 4; ++i) {
        int d = tid + i * 256;
        float acc = cb[d];
#pragma unroll
        for (int dy = -1; dy <= 1; ++dy) {
            int hh = h + dy;
            if ((unsigned)hh >= 32u) continue;
#pragma unroll
            for (int dx = -1; dx <= 1; ++dx) {
                int ww = w + dx;
                if ((unsigned)ww >= 32u) continue;
                int ln = (hh << 5) | ww;
                acc += g_xz[((size_t)(b * L_ + ln)) * (2 * DI_) + d] *
                       cw[d * 9 + (dy + 1) * 3 + (dx + 1)];
            }
        }
        float s = acc / (1.0f + __expf(-acc));
        g_xc[((size_t)(b * L_ + l)) * DI_ + d] = s;
    }
}

// ---------------- x_dbl[bk, t, c] = sum_d xc[b, map_k(t), d] * xpw[k, c, d] ----------------
__global__ void __launch_bounds__(256) xdbl_kernel(const float* __restrict__ xpw) {
    int k = blockIdx.y, b = blockIdx.z;
    int t0 = blockIdx.x * 64;
    int bk = b * K_ + k;
    __shared__ float As[32][68];  // [d][t]
    __shared__ float Ws[32][68];  // [d][c]
    int tid = threadIdx.x;
    int tx = tid & 15, ty = tid >> 4;
    const float* wbase = xpw + (size_t)k * 64 * DI_;
    float acc[4][4];
#pragma unroll
    for (int i = 0; i < 4; ++i)
#pragma unroll
        for (int j = 0; j < 4; ++j) acc[i][j] = 0.0f;

    for (int dk = 0; dk < DI_; dk += 32) {
#pragma unroll
        for (int it = 0; it < 2; ++it) {
            int t4 = tid + it * 256;
            int row = t4 >> 3;
            int dc = (t4 & 7) << 2;
            int lsp = map_t(k, t0 + row);
            float4 va = *(const float4*)(g_xc + ((size_t)b * L_ + lsp) * DI_ + dk + dc);
            As[dc + 0][row] = va.x; As[dc + 1][row] = va.y;
            As[dc + 2][row] = va.z; As[dc + 3][row] = va.w;
            float4 vw = *(const float4*)(wbase + (size_t)row * DI_ + dk + dc);
            Ws[dc + 0][row] = vw.x; Ws[dc + 1][row] = vw.y;
            Ws[dc + 2][row] = vw.z; Ws[dc + 3][row] = vw.w;
        }
        __syncthreads();
#pragma unroll
        for (int dd = 0; dd < 32; ++dd) {
            float4 a = *(const float4*)&As[dd][ty * 4];
            float4 w4 = *(const float4*)&Ws[dd][tx * 4];
            float av[4] = {a.x, a.y, a.z, a.w};
            float wv[4] = {w4.x, w4.y, w4.z, w4.w};
#pragma unroll
            for (int i = 0; i < 4; ++i)
#pragma unroll
                for (int j = 0; j < 4; ++j)
                    acc[i][j] = fmaf(av[i], wv[j], acc[i][j]);
        }
        __syncthreads();
    }
#pragma unroll
    for (int i = 0; i < 4; ++i) {
        float4 v;
        v.x = acc[i][0]; v.y = acc[i][1]; v.z = acc[i][2]; v.w = acc[i][3];
        *(float4*)(g_xdbl + ((size_t)bk * L_ + t0 + ty * 4 + i) * 64 + tx * 4) = v;
    }
}

// ---------------- dts[bk, t, d] = softplus( sum_r xdbl[bk,t,r]*dtw[k,d,r] + dtb[k,d] ) ------
__global__ void __launch_bounds__(256) dts_kernel(const float* __restrict__ dtw,
                                                  const float* __restrict__ dtb) {
    int bk = blockIdx.z;
    int k = bk & 3;
    int t0 = blockIdx.y * 64, d0 = blockIdx.x * 64;
    __shared__ float As[32][68];  // [r][t]
    __shared__ float Ws[32][68];  // [r][d]
    int tid = threadIdx.x;
    int tx = tid & 15, ty = tid >> 4;
#pragma unroll
    for (int it = 0; it < 2; ++it) {
        int t4 = tid + it * 256;
        int row = t4 >> 3;
        int rc = (t4 & 7) << 2;
        float4 va = *(const float4*)(g_xdbl + ((size_t)bk * L_ + t0 + row) * 64 + rc);
        As[rc + 0][row] = va.x; As[rc + 1][row] = va.y;
        As[rc + 2][row] = va.z; As[rc + 3][row] = va.w;
        float4 vw = *(const float4*)(dtw + ((size_t)(k * DI_ + d0 + row)) * R_ + rc);
        Ws[rc + 0][row] = vw.x; Ws[rc + 1][row] = vw.y;
        Ws[rc + 2][row] = vw.z; Ws[rc + 3][row] = vw.w;
    }
    __syncthreads();
    float acc[4][4];
#pragma unroll
    for (int i = 0; i < 4; ++i)
#pragma unroll
        for (int j = 0; j < 4; ++j) acc[i][j] = 0.0f;
#pragma unroll
    for (int r = 0; r < 32; ++r) {
        float4 a = *(const float4*)&As[r][ty * 4];
        float4 w4 = *(const float4*)&Ws[r][tx * 4];
        float av[4] = {a.x, a.y, a.z, a.w};
        float wv[4] = {w4.x, w4.y, w4.z, w4.w};
#pragma unroll
        for (int i = 0; i < 4; ++i)
#pragma unroll
            for (int j = 0; j < 4; ++j)
                acc[i][j] = fmaf(av[i], wv[j], acc[i][j]);
    }
#pragma unroll
    for (int i = 0; i < 4; ++i) {
        float4 v;
#pragma unroll
        for (int j = 0; j < 4; ++j) {
            int d = d0 + tx * 4 + j;
            float val = acc[i][j] + dtb[k * DI_ + d];
            float sp = (val > 20.0f) ? val : log1pf(__expf(val));
            ((float*)&v)[j] = sp;
        }
        *(float4*)(g_dts + ((size_t)bk * L_ + t0 + ty * 4 + i) * DI_ + d0 + tx * 4) = v;
    }
}

// ---------------- selective scan (sequential over t, thread = (b,k,d)) ----------------
__global__ void __launch_bounds__(256) scan_kernel(const float* __restrict__ A_logs,
                                                   const float* __restrict__ Ds) {
    int b = blockIdx.z, k = blockIdx.y;
    int d = blockIdx.x * 256 + threadIdx.x;
    int bk = b * K_ + k;
    int row = k * DI_ + d;

    float An[N_];
#pragma unroll
    for (int n = 0; n < N_; ++n) An[n] = -__expf(A_logs[(size_t)row * N_ + n]);
    float Dv = Ds[row];
    float h[N_];
#pragma unroll
    for (int n = 0; n < N_; ++n) h[n] = 0.0f;

    const float* xd = g_xdbl + (size_t)bk * L_ * 64;
    const float* dtp = g_dts + (size_t)bk * L_ * DI_;
    float* ysk = g_ys + (size_t)bk * L_ * DI_;
    const float* xcb = g_xc + (size_t)b * L_ * DI_;

    for (int t = 0; t < L_; ++t) {
        int l = map_t(k, t);
        float u = xcb[(size_t)l * DI_ + d];
        float dt = dtp[(size_t)t * DI_ + d];

        float bc[32];
        const float4* p = (const float4*)(xd + t * 64 + 32);
#pragma unroll
        for (int j = 0; j < 8; ++j) {
            float4 v = p[j];
            bc[4 * j + 0] = v.x; bc[4 * j + 1] = v.y;
            bc[4 * j + 2] = v.z; bc[4 * j + 3] = v.w;
        }
        float du = dt * u;
        float y = Dv * u;
#pragma unroll
        for (int n = 0; n < N_; ++n) {
            float dA = __expf(dt * An[n]);
            h[n] = h[n] * dA + du * bc[n];
            y = fmaf(h[n], bc[16 + n], y);
        }
        ysk[(size_t)l * DI_ + d] = y;
    }
}

// ---------------- combine 4 dirs + out-layernorm + silu(z) gate ----------------
__global__ void __launch_bounds__(256) combine_kernel(const float* __restrict__ onw,
                                                      const float* __restrict__ onb) {
    int bl = blockIdx.x;
    int b = bl >> 10;
    int l = bl & 1023;
    int tid = threadIdx.x;
    int d0 = tid * 4;

    float4 acc4 = make_float4(0.f, 0.f, 0.f, 0.f);
#pragma unroll
    for (int k = 0; k < K_; ++k) {
        float4 t = *(const float4*)(g_ys + (((size_t)(b * K_ + k)) * L_ + l) * DI_ + d0);
        acc4.x += t.x; acc4.y += t.y; acc4.z += t.z; acc4.w += t.w;
    }
    float s = acc4.x + acc4.y + acc4.z + acc4.w;
    float q = acc4.x * acc4.x + acc4.y * acc4.y + acc4.z * acc4.z + acc4.w * acc4.w;
#pragma unroll
    for (int o = 16; o; o >>= 1) {
        s += __shfl_xor_sync(0xffffffffu, s, o);
        q += __shfl_xor_sync(0xffffffffu, q, o);
    }
    __shared__ float shs[8], shq[8];
    if ((tid & 31) == 0) { shs[tid >> 5] = s; shq[tid >> 5] = q; }
    __syncthreads();
    float S = 0.f, Q = 0.f;
#pragma unroll
    for (int i = 0; i < 8; ++i) { S += shs[i]; Q += shq[i]; }
    float mu  = S * (1.0f / DI_);
    float var = Q * (1.0f / DI_) - mu * mu;
    float rs  = rsqrtf(var + 1e-5f);

    float4 wv = *(const float4*)(onw + d0);
    float4 bv = *(const float4*)(onb + d0);
    float4 zv = *(const float4*)(g_xz + (size_t)bl * (2 * DI_) + DI_ + d0);
    float4 o;
    {
        float ln0 = (acc4.x - mu) * rs * wv.x + bv.x;
        float ln1 = (acc4.y - mu) * rs * wv.y + bv.y;
        float ln2 = (acc4.z - mu) * rs * wv.z + bv.z;
        float ln3 = (acc4.w - mu) * rs * wv.w + bv.w;
        o.x = ln0 * (zv.x / (1.0f + __expf(-zv.x)));
        o.y = ln1 * (zv.y / (1.0f + __expf(-zv.y)));
        o.z = ln2 * (zv.z / (1.0f + __expf(-zv.z)));
        o.w = ln3 * (zv.w / (1.0f + __expf(-zv.w)));
    }
    *(float4*)(g_yf + (size_t)bl * DI_ + d0) = o;
}

// ---------------- launch ----------------
extern "C" void kernel_launch(void* const* d_in, const int* in_sizes, int n_in,
                              void* d_out, int out_size) {
    const float* x          = (const float*)d_in[0];
    const float* norm_w     = (const float*)d_in[1];
    const float* norm_b     = (const float*)d_in[2];
    const float* in_proj_w  = (const float*)d_in[3];
    const float* conv_w     = (const float*)d_in[4];
    const float* conv_b     = (const float*)d_in[5];
    const float* x_proj_w   = (const float*)d_in[6];
    const float* dt_projs_w = (const float*)d_in[7];
    const float* dt_projs_b = (const float*)d_in[8];
    const float* A_logs     = (const float*)d_in[9];
    const float* Ds         = (const float*)d_in[10];
    const float* out_norm_w = (const float*)d_in[11];
    const float* out_norm_b = (const float*)d_in[12];
    const float* out_proj_w = (const float*)d_in[13];
    float* out = (float*)d_out;

    ln_kernel<<<ML_, 128>>>(x, norm_w, norm_b);
    sgemm_nt<0><<<dim3((2 * DI_) / 128, ML_ / 128), 256>>>(in_proj_w, nullptr, nullptr);
    conv_kernel<<<dim3(L_, B_), 256>>>(conv_w, conv_b);
    xdbl_kernel<<<dim3(L_ / 64, K_, B_), 256>>>(x_proj_w);
    dts_kernel<<<dim3(DI_ / 64, L_ / 64, B_ * K_), 256>>>(dt_projs_w, dt_projs_b);
    scan_kernel<<<dim3(DI_ / 256, K_, B_), 256>>>(A_logs, Ds);
    combine_kernel<<<ML_, 256>>>(out_norm_w, out_norm_b);
    sgemm_nt<1><<<dim3(C_ / 128, ML_ / 128), 256>>>(out_proj_w, x, out);
}

// round 4
// speedup vs baseline: 1.5144x; 1.5144x over previous
#include <cuda_runtime.h>
#include <cuda_fp16.h>
#include <math.h>
#include <stdint.h>

// ---------------- problem constants ----------------
#define B_   8
#define H_   32
#define W_   32
#define L_   1024
#define C_   512
#define DI_  1024
#define K_   4
#define N_   16
#define R_   32
#define ML_  (B_ * L_)          // 8192 rows

// ---------------- scratch (device globals) ----------------
__device__ __half g_xnh [(size_t)ML_ * C_];            // layernorm(x)  (half)
__device__ __half g_xzh [(size_t)ML_ * 2 * DI_];       // in_proj out   (half)
__device__ __half g_xch [(size_t)ML_ * DI_];           // conv+silu     (half)
__device__ float  g_xdbl[(size_t)B_ * K_ * L_ * 64];   // (bk, t, c)    fp32
__device__ __half g_dtsh[(size_t)B_ * K_ * L_ * DI_];  // (bk, t, d)    half
__device__ __half g_ysh [(size_t)B_ * K_ * L_ * DI_];  // (bk, l, d)    half
__device__ __half g_yfh [(size_t)ML_ * DI_];           // pre-out_proj  half
__device__ __half g_wA  [2 * DI_ * C_];                // in_proj_w  half
__device__ __half g_wB  [C_ * DI_];                    // out_proj_w half
__device__ __half g_wX  [K_ * 64 * DI_];               // x_proj_w   half

// scan index map: spatial l for direction k at scan step t
__device__ __forceinline__ int map_t(int k, int t) {
    int tt = (k & 2) ? (L_ - 1 - t) : t;
    return (k & 1) ? (((tt & 31) << 5) | (tt >> 5)) : tt;
}

__device__ __forceinline__ uint32_t smem_u32(const void* p) {
    return (uint32_t)__cvta_generic_to_shared(p);
}
__device__ __forceinline__ void ldsm4(uint32_t* r, uint32_t addr) {
    asm volatile("ldmatrix.sync.aligned.m8n8.x4.shared.b16 {%0,%1,%2,%3}, [%4];"
                 : "=r"(r[0]), "=r"(r[1]), "=r"(r[2]), "=r"(r[3]) : "r"(addr));
}
__device__ __forceinline__ void mma16816(float* c, const uint32_t* a, const uint32_t* b) {
    asm volatile("mma.sync.aligned.m16n8k16.row.col.f32.f16.f16.f32 "
                 "{%0,%1,%2,%3}, {%4,%5,%6,%7}, {%8,%9}, {%0,%1,%2,%3};"
                 : "+f"(c[0]), "+f"(c[1]), "+f"(c[2]), "+f"(c[3])
                 : "r"(a[0]), "r"(a[1]), "r"(a[2]), "r"(a[3]), "r"(b[0]), "r"(b[1]));
}

// ---------------- weight fp32 -> fp16 convert ----------------
__global__ void __launch_bounds__(256) convert_kernel(const float* __restrict__ ipw,
                                                      const float* __restrict__ opw,
                                                      const float* __restrict__ xpw) {
    int i = blockIdx.x * 256 + threadIdx.x;
    if (i < 2 * DI_ * C_) g_wA[i] = __float2half_rn(ipw[i]);
    if (i < C_ * DI_)     g_wB[i] = __float2half_rn(opw[i]);
    if (i < K_ * 64 * DI_) g_wX[i] = __float2half_rn(xpw[i]);
}

// ---------------- input layernorm (row = 512) -> half ----------------
__global__ void __launch_bounds__(128) ln_kernel(const float* __restrict__ x,
                                                 const float* __restrict__ w,
                                                 const float* __restrict__ bb) {
    int bl = blockIdx.x;
    int tid = threadIdx.x;
    const float* xr = x + (size_t)bl * C_;
    float4 v = *(const float4*)(xr + tid * 4);
    float s = v.x + v.y + v.z + v.w;
    float q = v.x * v.x + v.y * v.y + v.z * v.z + v.w * v.w;
#pragma unroll
    for (int o = 16; o; o >>= 1) {
        s += __shfl_xor_sync(0xffffffffu, s, o);
        q += __shfl_xor_sync(0xffffffffu, q, o);
    }
    __shared__ float shs[4], shq[4];
    if ((tid & 31) == 0) { shs[tid >> 5] = s; shq[tid >> 5] = q; }
    __syncthreads();
    float S = shs[0] + shs[1] + shs[2] + shs[3];
    float Q = shq[0] + shq[1] + shq[2] + shq[3];
    float mu  = S * (1.0f / C_);
    float var = Q * (1.0f / C_) - mu * mu;
    float rs  = rsqrtf(var + 1e-5f);
    float4 wv = *(const float4*)(w + tid * 4);
    float4 bv = *(const float4*)(bb + tid * 4);
    float o0 = (v.x - mu) * rs * wv.x + bv.x;
    float o1 = (v.y - mu) * rs * wv.y + bv.y;
    float o2 = (v.z - mu) * rs * wv.z + bv.z;
    float o3 = (v.w - mu) * rs * wv.w + bv.w;
    __half* dst = g_xnh + (size_t)bl * C_ + tid * 4;
    *(__half2*)(dst)     = __floats2half2_rn(o0, o1);
    *(__half2*)(dst + 2) = __floats2half2_rn(o2, o3);
}

// ---------------- tensor-core NT hgemm: BM=128, BN=128, BK=32 ----------------
// MODE 0: A=g_xnh (K=512),  W=g_wA, out -> g_xzh (half, N=2048)
// MODE 1: A=g_yfh (K=1024), W=g_wB, out -> Cout fp32 (+resid, N=512)
template <int MODE>
__global__ void __launch_bounds__(256) hgemm_nt(const float* __restrict__ resid,
                                                float* __restrict__ Cout) {
    constexpr int Kd = (MODE == 0) ? C_ : DI_;
    constexpr int Nd = (MODE == 0) ? 2 * DI_ : C_;
    const __half* A = (MODE == 0) ? g_xnh : g_yfh;
    const __half* Wh = (MODE == 0) ? g_wA : g_wB;

    __shared__ __half As[128][40];
    __shared__ __half Bs[128][40];

    int tid = threadIdx.x;
    int lane = tid & 31, wid = tid >> 5;
    int wm = wid & 1, wn = wid >> 1;        // 2 x 4 warp grid: warp tile 64m x 32n
    int m0 = blockIdx.y * 128, n0 = blockIdx.x * 128;

    float c[4][4][4];
#pragma unroll
    for (int i = 0; i < 4; ++i)
#pragma unroll
        for (int j = 0; j < 4; ++j)
#pragma unroll
            for (int e = 0; e < 4; ++e) c[i][j][e] = 0.0f;

    for (int k0 = 0; k0 < Kd; k0 += 32) {
#pragma unroll
        for (int it = 0; it < 2; ++it) {
            int idx = tid + it * 256;
            int row = idx >> 2;
            int seg = (idx & 3) * 8;
            *(uint4*)&As[row][seg] = *(const uint4*)(A + (size_t)(m0 + row) * Kd + k0 + seg);
            *(uint4*)&Bs[row][seg] = *(const uint4*)(Wh + (size_t)(n0 + row) * Kd + k0 + seg);
        }
        __syncthreads();
#pragma unroll
        for (int kk = 0; kk < 2; ++kk) {
            uint32_t a[4][4];
#pragma unroll
            for (int mi = 0; mi < 4; ++mi) {
                uint32_t addr = smem_u32(&As[wm * 64 + mi * 16 + (lane & 15)]
                                           [kk * 16 + ((lane >> 4) << 3)]);
                ldsm4(a[mi], addr);
            }
            uint32_t bfr[4][2];
#pragma unroll
            for (int nj = 0; nj < 2; ++nj) {
                int n_off = (lane & 7) + ((lane >> 4) << 3);
                int kh = ((lane >> 3) & 1) * 8;
                uint32_t addr = smem_u32(&Bs[wn * 32 + nj * 16 + n_off][kk * 16 + kh]);
                uint32_t t4[4];
                ldsm4(t4, addr);
                bfr[2 * nj][0] = t4[0]; bfr[2 * nj][1] = t4[1];
                bfr[2 * nj + 1][0] = t4[2]; bfr[2 * nj + 1][1] = t4[3];
            }
#pragma unroll
            for (int mi = 0; mi < 4; ++mi)
#pragma unroll
                for (int ni = 0; ni < 4; ++ni)
                    mma16816(c[mi][ni], a[mi], bfr[ni]);
        }
        __syncthreads();
    }

#pragma unroll
    for (int mi = 0; mi < 4; ++mi) {
#pragma unroll
        for (int ni = 0; ni < 4; ++ni) {
            int r0 = m0 + wm * 64 + mi * 16 + (lane >> 2);
            int cc = n0 + wn * 32 + ni * 8 + ((lane & 3) << 1);
            if (MODE == 0) {
                *(__half2*)(g_xzh + (size_t)r0 * Nd + cc) =
                    __floats2half2_rn(c[mi][ni][0], c[mi][ni][1]);
                *(__half2*)(g_xzh + (size_t)(r0 + 8) * Nd + cc) =
                    __floats2half2_rn(c[mi][ni][2], c[mi][ni][3]);
            } else {
                float2 ra = *(const float2*)(resid + (size_t)r0 * Nd + cc);
                float2 rb = *(const float2*)(resid + (size_t)(r0 + 8) * Nd + cc);
                float2 oa = make_float2(c[mi][ni][0] + ra.x, c[mi][ni][1] + ra.y);
                float2 ob = make_float2(c[mi][ni][2] + rb.x, c[mi][ni][3] + rb.y);
                *(float2*)(Cout + (size_t)r0 * Nd + cc) = oa;
                *(float2*)(Cout + (size_t)(r0 + 8) * Nd + cc) = ob;
            }
        }
    }
}

// ---------------- depthwise 3x3 conv + bias + silu (half in/out) ----------------
__global__ void __launch_bounds__(256) conv_kernel(const float* __restrict__ cw,
                                                   const float* __restrict__ cb) {
    int l = blockIdx.x, b = blockIdx.y;
    int h = l >> 5, w = l & 31;
    int tid = threadIdx.x;
#pragma unroll
    for (int i = 0; i < 4; ++i) {
        int d = tid + i * 256;
        float acc = cb[d];
#pragma unroll
        for (int dy = -1; dy <= 1; ++dy) {
            int hh = h + dy;
            if ((unsigned)hh >= 32u) continue;
#pragma unroll
            for (int dx = -1; dx <= 1; ++dx) {
                int ww = w + dx;
                if ((unsigned)ww >= 32u) continue;
                int ln = (hh << 5) | ww;
                acc += __half2float(g_xzh[((size_t)(b * L_ + ln)) * (2 * DI_) + d]) *
                       cw[d * 9 + (dy + 1) * 3 + (dx + 1)];
            }
        }
        float s = acc / (1.0f + __expf(-acc));
        g_xch[((size_t)(b * L_ + l)) * DI_ + d] = __float2half_rn(s);
    }
}

// ---------------- x_dbl via tensor cores: BM=128(t), BN=64(c), BK=32, gather rows ----
__global__ void __launch_bounds__(256) xdbl_kernel() {
    int k = blockIdx.y, b = blockIdx.z;
    int t0 = blockIdx.x * 128;
    int bk = b * K_ + k;

    __shared__ __half As[128][40];
    __shared__ __half Bs[64][40];

    int tid = threadIdx.x;
    int lane = tid & 31, wid = tid >> 5;
    int wm = wid & 3, wn = wid >> 2;        // 4 x 2 warp grid: warp tile 32m x 32n

    const __half* xcb = g_xch + (size_t)b * L_ * DI_;
    const __half* Wh = g_wX + (size_t)k * 64 * DI_;

    float c[2][4][4];
#pragma unroll
    for (int i = 0; i < 2; ++i)
#pragma unroll
        for (int j = 0; j < 4; ++j)
#pragma unroll
            for (int e = 0; e < 4; ++e) c[i][j][e] = 0.0f;

    for (int dk = 0; dk < DI_; dk += 32) {
#pragma unroll
        for (int it = 0; it < 2; ++it) {
            int idx = tid + it * 256;
            int row = idx >> 2;
            int seg = (idx & 3) * 8;
            int lsp = map_t(k, t0 + row);
            *(uint4*)&As[row][seg] = *(const uint4*)(xcb + (size_t)lsp * DI_ + dk + seg);
        }
        {
            int row = tid >> 2;
            int seg = (tid & 3) * 8;
            *(uint4*)&Bs[row][seg] = *(const uint4*)(Wh + (size_t)row * DI_ + dk + seg);
        }
        __syncthreads();
#pragma unroll
        for (int kk = 0; kk < 2; ++kk) {
            uint32_t a[2][4];
#pragma unroll
            for (int mi = 0; mi < 2; ++mi) {
                uint32_t addr = smem_u32(&As[wm * 32 + mi * 16 + (lane & 15)]
                                           [kk * 16 + ((lane >> 4) << 3)]);
                ldsm4(a[mi], addr);
            }
            uint32_t bfr[4][2];
#pragma unroll
            for (int nj = 0; nj < 2; ++nj) {
                int n_off = (lane & 7) + ((lane >> 4) << 3);
                int kh = ((lane >> 3) & 1) * 8;
                uint32_t addr = smem_u32(&Bs[wn * 32 + nj * 16 + n_off][kk * 16 + kh]);
                uint32_t t4[4];
                ldsm4(t4, addr);
                bfr[2 * nj][0] = t4[0]; bfr[2 * nj][1] = t4[1];
                bfr[2 * nj + 1][0] = t4[2]; bfr[2 * nj + 1][1] = t4[3];
            }
#pragma unroll
            for (int mi = 0; mi < 2; ++mi)
#pragma unroll
                for (int ni = 0; ni < 4; ++ni)
                    mma16816(c[mi][ni], a[mi], bfr[ni]);
        }
        __syncthreads();
    }

    float* outb = g_xdbl + ((size_t)bk * L_ + t0) * 64;
#pragma unroll
    for (int mi = 0; mi < 2; ++mi) {
#pragma unroll
        for (int ni = 0; ni < 4; ++ni) {
            int r0 = wm * 32 + mi * 16 + (lane >> 2);
            int cc = wn * 32 + ni * 8 + ((lane & 3) << 1);
            *(float2*)(outb + (size_t)r0 * 64 + cc) = make_float2(c[mi][ni][0], c[mi][ni][1]);
            *(float2*)(outb + (size_t)(r0 + 8) * 64 + cc) = make_float2(c[mi][ni][2], c[mi][ni][3]);
        }
    }
}

// ---------------- dts[bk,t,d] = softplus( xdbl[bk,t,0:32] . dtw[k,d,:] + dtb[k,d] ) ----
__global__ void __launch_bounds__(256) dts_kernel(const float* __restrict__ dtw,
                                                  const float* __restrict__ dtb) {
    int bk = blockIdx.z;
    int k = bk & 3;
    int t0 = blockIdx.y * 64, d0 = blockIdx.x * 64;
    __shared__ float As[32][68];  // [r][t]
    __shared__ float Ws[32][68];  // [r][d]
    int tid = threadIdx.x;
    int tx = tid & 15, ty = tid >> 4;
#pragma unroll
    for (int it = 0; it < 2; ++it) {
        int t4 = tid + it * 256;
        int row = t4 >> 3;
        int rc = (t4 & 7) << 2;
        float4 va = *(const float4*)(g_xdbl + ((size_t)bk * L_ + t0 + row) * 64 + rc);
        As[rc + 0][row] = va.x; As[rc + 1][row] = va.y;
        As[rc + 2][row] = va.z; As[rc + 3][row] = va.w;
        float4 vw = *(const float4*)(dtw + ((size_t)(k * DI_ + d0 + row)) * R_ + rc);
        Ws[rc + 0][row] = vw.x; Ws[rc + 1][row] = vw.y;
        Ws[rc + 2][row] = vw.z; Ws[rc + 3][row] = vw.w;
    }
    __syncthreads();
    float acc[4][4];
#pragma unroll
    for (int i = 0; i < 4; ++i)
#pragma unroll
        for (int j = 0; j < 4; ++j) acc[i][j] = 0.0f;
#pragma unroll
    for (int r = 0; r < 32; ++r) {
        float4 a = *(const float4*)&As[r][ty * 4];
        float4 w4 = *(const float4*)&Ws[r][tx * 4];
        float av[4] = {a.x, a.y, a.z, a.w};
        float wv[4] = {w4.x, w4.y, w4.z, w4.w};
#pragma unroll
        for (int i = 0; i < 4; ++i)
#pragma unroll
            for (int j = 0; j < 4; ++j)
                acc[i][j] = fmaf(av[i], wv[j], acc[i][j]);
    }
#pragma unroll
    for (int i = 0; i < 4; ++i) {
        float sp[4];
#pragma unroll
        for (int j = 0; j < 4; ++j) {
            int d = d0 + tx * 4 + j;
            float val = acc[i][j] + dtb[k * DI_ + d];
            sp[j] = (val > 20.0f) ? val : log1pf(__expf(val));
        }
        __half* dst = g_dtsh + ((size_t)bk * L_ + t0 + ty * 4 + i) * DI_ + d0 + tx * 4;
        *(__half2*)(dst)     = __floats2half2_rn(sp[0], sp[1]);
        *(__half2*)(dst + 2) = __floats2half2_rn(sp[2], sp[3]);
    }
}

// ---------------- selective scan (sequential over t, thread = (b,k,d)) ----------------
__global__ void __launch_bounds__(256) scan_kernel(const float* __restrict__ A_logs,
                                                   const float* __restrict__ Ds) {
    int b = blockIdx.z, k = blockIdx.y;
    int d = blockIdx.x * 256 + threadIdx.x;
    int bk = b * K_ + k;
    int row = k * DI_ + d;

    float An[N_];
#pragma unroll
    for (int n = 0; n < N_; ++n) An[n] = -__expf(A_logs[(size_t)row * N_ + n]);
    float Dv = Ds[row];
    float h[N_];
#pragma unroll
    for (int n = 0; n < N_; ++n) h[n] = 0.0f;

    const float* xd = g_xdbl + (size_t)bk * L_ * 64;
    const __half* dtp = g_dtsh + (size_t)bk * L_ * DI_;
    __half* ysk = g_ysh + (size_t)bk * L_ * DI_;
    const __half* xcb = g_xch + (size_t)b * L_ * DI_;

    for (int t = 0; t < L_; ++t) {
        int l = map_t(k, t);
        float u = __half2float(xcb[(size_t)l * DI_ + d]);
        float dt = __half2float(dtp[(size_t)t * DI_ + d]);

        float bc[32];
        const float4* p = (const float4*)(xd + t * 64 + 32);
#pragma unroll
        for (int j = 0; j < 8; ++j) {
            float4 v = p[j];
            bc[4 * j + 0] = v.x; bc[4 * j + 1] = v.y;
            bc[4 * j + 2] = v.z; bc[4 * j + 3] = v.w;
        }
        float du = dt * u;
        float y = Dv * u;
#pragma unroll
        for (int n = 0; n < N_; ++n) {
            float dA = __expf(dt * An[n]);
            h[n] = h[n] * dA + du * bc[n];
            y = fmaf(h[n], bc[16 + n], y);
        }
        ysk[(size_t)l * DI_ + d] = __float2half_rn(y);
    }
}

// ---------------- combine 4 dirs + out-layernorm + silu(z) gate -> half ----------------
__global__ void __launch_bounds__(256) combine_kernel(const float* __restrict__ onw,
                                                      const float* __restrict__ onb) {
    int bl = blockIdx.x;
    int b = bl >> 10;
    int l = bl & 1023;
    int tid = threadIdx.x;
    int d0 = tid * 4;

    float a0 = 0.f, a1 = 0.f, a2 = 0.f, a3 = 0.f;
#pragma unroll
    for (int k = 0; k < K_; ++k) {
        const __half* p = g_ysh + (((size_t)(b * K_ + k)) * L_ + l) * DI_ + d0;
        __half2 h01 = *(const __half2*)(p);
        __half2 h23 = *(const __half2*)(p + 2);
        float2 f01 = __half22float2(h01);
        float2 f23 = __half22float2(h23);
        a0 += f01.x; a1 += f01.y; a2 += f23.x; a3 += f23.y;
    }
    float s = a0 + a1 + a2 + a3;
    float q = a0 * a0 + a1 * a1 + a2 * a2 + a3 * a3;
#pragma unroll
    for (int o = 16; o; o >>= 1) {
        s += __shfl_xor_sync(0xffffffffu, s, o);
        q += __shfl_xor_sync(0xffffffffu, q, o);
    }
    __shared__ float shs[8], shq[8];
    if ((tid & 31) == 0) { shs[tid >> 5] = s; shq[tid >> 5] = q; }
    __syncthreads();
    float S = 0.f, Q = 0.f;
#pragma unroll
    for (int i = 0; i < 8; ++i) { S += shs[i]; Q += shq[i]; }
    float mu  = S * (1.0f / DI_);
    float var = Q * (1.0f / DI_) - mu * mu;
    float rs  = rsqrtf(var + 1e-5f);

    float4 wv = *(const float4*)(onw + d0);
    float4 bv = *(const float4*)(onb + d0);
    const __half* zp = g_xzh + (size_t)bl * (2 * DI_) + DI_ + d0;
    float2 z01 = __half22float2(*(const __half2*)(zp));
    float2 z23 = __half22float2(*(const __half2*)(zp + 2));

    float ln0 = (a0 - mu) * rs * wv.x + bv.x;
    float ln1 = (a1 - mu) * rs * wv.y + bv.y;
    float ln2 = (a2 - mu) * rs * wv.z + bv.z;
    float ln3 = (a3 - mu) * rs * wv.w + bv.w;
    float o0 = ln0 * (z01.x / (1.0f + __expf(-z01.x)));
    float o1 = ln1 * (z01.y / (1.0f + __expf(-z01.y)));
    float o2 = ln2 * (z23.x / (1.0f + __expf(-z23.x)));
    float o3 = ln3 * (z23.y / (1.0f + __expf(-z23.y)));

    __half* dst = g_yfh + (size_t)bl * DI_ + d0;
    *(__half2*)(dst)     = __floats2half2_rn(o0, o1);
    *(__half2*)(dst + 2) = __floats2half2_rn(o2, o3);
}

// ---------------- launch ----------------
extern "C" void kernel_launch(void* const* d_in, const int* in_sizes, int n_in,
                              void* d_out, int out_size) {
    const float* x          = (const float*)d_in[0];
    const float* norm_w     = (const float*)d_in[1];
    const float* norm_b     = (const float*)d_in[2];
    const float* in_proj_w  = (const float*)d_in[3];
    const float* conv_w     = (const float*)d_in[4];
    const float* conv_b     = (const float*)d_in[5];
    const float* x_proj_w   = (const float*)d_in[6];
    const float* dt_projs_w = (const float*)d_in[7];
    const float* dt_projs_b = (const float*)d_in[8];
    const float* A_logs     = (const float*)d_in[9];
    const float* Ds         = (const float*)d_in[10];
    const float* out_norm_w = (const float*)d_in[11];
    const float* out_norm_b = (const float*)d_in[12];
    const float* out_proj_w = (const float*)d_in[13];
    float* out = (float*)d_out;

    convert_kernel<<<(2 * DI_ * C_) / 256, 256>>>(in_proj_w, out_proj_w, x_proj_w);
    ln_kernel<<<ML_, 128>>>(x, norm_w, norm_b);
    hgemm_nt<0><<<dim3((2 * DI_) / 128, ML_ / 128), 256>>>(nullptr, nullptr);
    conv_kernel<<<dim3(L_, B_), 256>>>(conv_w, conv_b);
    xdbl_kernel<<<dim3(L_ / 128, K_, B_), 256>>>();
    dts_kernel<<<dim3(DI_ / 64, L_ / 64, B_ * K_), 256>>>(dt_projs_w, dt_projs_b);
    scan_kernel<<<dim3(DI_ / 256, K_, B_), 256>>>(A_logs, Ds);
    combine_kernel<<<ML_, 256>>>(out_norm_w, out_norm_b);
    hgemm_nt<1><<<dim3(C_ / 128, ML_ / 128), 256>>>(x, out);
}

// round 5
// speedup vs baseline: 2.0980x; 1.3853x over previous
#include <cuda_runtime.h>
#include <cuda_fp16.h>
#include <math.h>
#include <stdint.h>

// ---------------- problem constants ----------------
#define B_   8
#define H_   32
#define W_   32
#define L_   1024
#define C_   512
#define DI_  1024
#define K_   4
#define N_   16
#define R_   32
#define ML_  (B_ * L_)          // 8192 rows

// ---------------- scratch (device globals) ----------------
__device__ __half g_xnh [(size_t)ML_ * C_];            // layernorm(x)  (half)
__device__ __half g_xzh [(size_t)ML_ * 2 * DI_];       // in_proj out   (half)
__device__ __half g_xch [(size_t)ML_ * DI_];           // conv+silu     (half)
__device__ float  g_xdbl[(size_t)B_ * K_ * L_ * 64];   // (bk, t, c)    fp32
__device__ __half g_dtsh[(size_t)B_ * K_ * L_ * DI_];  // (bk, t, d)    half
__device__ __half g_ysh [(size_t)B_ * K_ * L_ * DI_];  // (bk, l, d)    half
__device__ __half g_yfh [(size_t)ML_ * DI_];           // pre-out_proj  half
__device__ __half g_wA  [2 * DI_ * C_];                // in_proj_w  half
__device__ __half g_wB  [C_ * DI_];                    // out_proj_w half
__device__ __half g_wX  [K_ * 64 * DI_];               // x_proj_w   half

// scan index map: spatial l for direction k at scan step t
__device__ __forceinline__ int map_t(int k, int t) {
    int tt = (k & 2) ? (L_ - 1 - t) : t;
    return (k & 1) ? (((tt & 31) << 5) | (tt >> 5)) : tt;
}

__device__ __forceinline__ uint32_t smem_u32(const void* p) {
    return (uint32_t)__cvta_generic_to_shared(p);
}
__device__ __forceinline__ void ldsm4(uint32_t* r, uint32_t addr) {
    asm volatile("ldmatrix.sync.aligned.m8n8.x4.shared.b16 {%0,%1,%2,%3}, [%4];"
                 : "=r"(r[0]), "=r"(r[1]), "=r"(r[2]), "=r"(r[3]) : "r"(addr));
}
__device__ __forceinline__ void mma16816(float* c, const uint32_t* a, const uint32_t* b) {
    asm volatile("mma.sync.aligned.m16n8k16.row.col.f32.f16.f16.f32 "
                 "{%0,%1,%2,%3}, {%4,%5,%6,%7}, {%8,%9}, {%0,%1,%2,%3};"
                 : "+f"(c[0]), "+f"(c[1]), "+f"(c[2]), "+f"(c[3])
                 : "r"(a[0]), "r"(a[1]), "r"(a[2]), "r"(a[3]), "r"(b[0]), "r"(b[1]));
}
__device__ __forceinline__ void cp16(uint32_t dst, const void* src) {
    asm volatile("cp.async.cg.shared.global [%0], [%1], 16;\n" :: "r"(dst), "l"(src));
}
#define CP_COMMIT() asm volatile("cp.async.commit_group;\n" ::: "memory")
#define CP_WAIT1()  asm volatile("cp.async.wait_group 1;\n" ::: "memory")
#define CP_WAIT0()  asm volatile("cp.async.wait_group 0;\n" ::: "memory")

// ---------------- weight fp32 -> fp16 convert ----------------
__global__ void __launch_bounds__(256) convert_kernel(const float* __restrict__ ipw,
                                                      const float* __restrict__ opw,
                                                      const float* __restrict__ xpw) {
    int i = blockIdx.x * 256 + threadIdx.x;
    if (i < 2 * DI_ * C_) g_wA[i] = __float2half_rn(ipw[i]);
    if (i < C_ * DI_)     g_wB[i] = __float2half_rn(opw[i]);
    if (i < K_ * 64 * DI_) g_wX[i] = __float2half_rn(xpw[i]);
}

// ---------------- input layernorm (row = 512) -> half ----------------
__global__ void __launch_bounds__(128) ln_kernel(const float* __restrict__ x,
                                                 const float* __restrict__ w,
                                                 const float* __restrict__ bb) {
    int bl = blockIdx.x;
    int tid = threadIdx.x;
    const float* xr = x + (size_t)bl * C_;
    float4 v = *(const float4*)(xr + tid * 4);
    float s = v.x + v.y + v.z + v.w;
    float q = v.x * v.x + v.y * v.y + v.z * v.z + v.w * v.w;
#pragma unroll
    for (int o = 16; o; o >>= 1) {
        s += __shfl_xor_sync(0xffffffffu, s, o);
        q += __shfl_xor_sync(0xffffffffu, q, o);
    }
    __shared__ float shs[4], shq[4];
    if ((tid & 31) == 0) { shs[tid >> 5] = s; shq[tid >> 5] = q; }
    __syncthreads();
    float S = shs[0] + shs[1] + shs[2] + shs[3];
    float Q = shq[0] + shq[1] + shq[2] + shq[3];
    float mu  = S * (1.0f / C_);
    float var = Q * (1.0f / C_) - mu * mu;
    float rs  = rsqrtf(var + 1e-5f);
    float4 wv = *(const float4*)(w + tid * 4);
    float4 bv = *(const float4*)(bb + tid * 4);
    float o0 = (v.x - mu) * rs * wv.x + bv.x;
    float o1 = (v.y - mu) * rs * wv.y + bv.y;
    float o2 = (v.z - mu) * rs * wv.z + bv.z;
    float o3 = (v.w - mu) * rs * wv.w + bv.w;
    __half* dst = g_xnh + (size_t)bl * C_ + tid * 4;
    *(__half2*)(dst)     = __floats2half2_rn(o0, o1);
    *(__half2*)(dst + 2) = __floats2half2_rn(o2, o3);
}

// ---------------- tensor-core NT hgemm, cp.async double-buffered ----------------
// MODE 0: A=g_xnh (K=512),  W=g_wA, out -> g_xzh (half, N=2048)
// MODE 1: A=g_yfh (K=1024), W=g_wB, out -> Cout fp32 (+resid, N=512)
template <int MODE>
__global__ void __launch_bounds__(256) hgemm_nt(const float* __restrict__ resid,
                                                float* __restrict__ Cout) {
    constexpr int Kd = (MODE == 0) ? C_ : DI_;
    constexpr int Nd = (MODE == 0) ? 2 * DI_ : C_;
    constexpr int NIT = Kd / 32;
    const __half* A = (MODE == 0) ? g_xnh : g_yfh;
    const __half* Wh = (MODE == 0) ? g_wA : g_wB;

    __shared__ __half As[2][128][40];
    __shared__ __half Bs[2][128][40];

    int tid = threadIdx.x;
    int lane = tid & 31, wid = tid >> 5;
    int wm = wid & 1, wn = wid >> 1;        // 2 x 4 warp grid: warp tile 64m x 32n
    int m0 = blockIdx.y * 128, n0 = blockIdx.x * 128;

    float c[4][4][4];
#pragma unroll
    for (int i = 0; i < 4; ++i)
#pragma unroll
        for (int j = 0; j < 4; ++j)
#pragma unroll
            for (int e = 0; e < 4; ++e) c[i][j][e] = 0.0f;

    int lrow = tid >> 2;
    int lseg = (tid & 3) * 8;
    const __half* pa0 = A + (size_t)(m0 + lrow) * Kd + lseg;
    const __half* pa1 = A + (size_t)(m0 + 64 + lrow) * Kd + lseg;
    const __half* pb0 = Wh + (size_t)(n0 + lrow) * Kd + lseg;
    const __half* pb1 = Wh + (size_t)(n0 + 64 + lrow) * Kd + lseg;

    // prologue: stage 0
    {
        cp16(smem_u32(&As[0][lrow][lseg]), pa0);
        cp16(smem_u32(&As[0][64 + lrow][lseg]), pa1);
        cp16(smem_u32(&Bs[0][lrow][lseg]), pb0);
        cp16(smem_u32(&Bs[0][64 + lrow][lseg]), pb1);
        CP_COMMIT();
    }

    for (int it = 0; it < NIT; ++it) {
        if (it + 1 < NIT) {
            int s = (it + 1) & 1;
            int k0 = (it + 1) * 32;
            cp16(smem_u32(&As[s][lrow][lseg]), pa0 + k0);
            cp16(smem_u32(&As[s][64 + lrow][lseg]), pa1 + k0);
            cp16(smem_u32(&Bs[s][lrow][lseg]), pb0 + k0);
            cp16(smem_u32(&Bs[s][64 + lrow][lseg]), pb1 + k0);
            CP_COMMIT();
            CP_WAIT1();
        } else {
            CP_WAIT0();
        }
        __syncthreads();
        int s = it & 1;
#pragma unroll
        for (int kk = 0; kk < 2; ++kk) {
            uint32_t a[4][4];
#pragma unroll
            for (int mi = 0; mi < 4; ++mi) {
                uint32_t addr = smem_u32(&As[s][wm * 64 + mi * 16 + (lane & 15)]
                                              [kk * 16 + ((lane >> 4) << 3)]);
                ldsm4(a[mi], addr);
            }
            uint32_t bfr[4][2];
#pragma unroll
            for (int nj = 0; nj < 2; ++nj) {
                int n_off = (lane & 7) + ((lane >> 4) << 3);
                int kh = ((lane >> 3) & 1) * 8;
                uint32_t addr = smem_u32(&Bs[s][wn * 32 + nj * 16 + n_off][kk * 16 + kh]);
                uint32_t t4[4];
                ldsm4(t4, addr);
                bfr[2 * nj][0] = t4[0]; bfr[2 * nj][1] = t4[1];
                bfr[2 * nj + 1][0] = t4[2]; bfr[2 * nj + 1][1] = t4[3];
            }
#pragma unroll
            for (int mi = 0; mi < 4; ++mi)
#pragma unroll
                for (int ni = 0; ni < 4; ++ni)
                    mma16816(c[mi][ni], a[mi], bfr[ni]);
        }
        __syncthreads();
    }

#pragma unroll
    for (int mi = 0; mi < 4; ++mi) {
#pragma unroll
        for (int ni = 0; ni < 4; ++ni) {
            int r0 = m0 + wm * 64 + mi * 16 + (lane >> 2);
            int cc = n0 + wn * 32 + ni * 8 + ((lane & 3) << 1);
            if (MODE == 0) {
                *(__half2*)(g_xzh + (size_t)r0 * Nd + cc) =
                    __floats2half2_rn(c[mi][ni][0], c[mi][ni][1]);
                *(__half2*)(g_xzh + (size_t)(r0 + 8) * Nd + cc) =
                    __floats2half2_rn(c[mi][ni][2], c[mi][ni][3]);
            } else {
                float2 ra = *(const float2*)(resid + (size_t)r0 * Nd + cc);
                float2 rb = *(const float2*)(resid + (size_t)(r0 + 8) * Nd + cc);
                float2 oa = make_float2(c[mi][ni][0] + ra.x, c[mi][ni][1] + ra.y);
                float2 ob = make_float2(c[mi][ni][2] + rb.x, c[mi][ni][3] + rb.y);
                *(float2*)(Cout + (size_t)r0 * Nd + cc) = oa;
                *(float2*)(Cout + (size_t)(r0 + 8) * Nd + cc) = ob;
            }
        }
    }
}

// ---------------- depthwise 3x3 conv + bias + silu (half in/out) ----------------
__global__ void __launch_bounds__(256) conv_kernel(const float* __restrict__ cw,
                                                   const float* __restrict__ cb) {
    int l = blockIdx.x, b = blockIdx.y;
    int h = l >> 5, w = l & 31;
    int tid = threadIdx.x;
#pragma unroll
    for (int i = 0; i < 4; ++i) {
        int d = tid + i * 256;
        float acc = cb[d];
#pragma unroll
        for (int dy = -1; dy <= 1; ++dy) {
            int hh = h + dy;
            if ((unsigned)hh >= 32u) continue;
#pragma unroll
            for (int dx = -1; dx <= 1; ++dx) {
                int ww = w + dx;
                if ((unsigned)ww >= 32u) continue;
                int ln = (hh << 5) | ww;
                acc += __half2float(g_xzh[((size_t)(b * L_ + ln)) * (2 * DI_) + d]) *
                       cw[d * 9 + (dy + 1) * 3 + (dx + 1)];
            }
        }
        float s = acc / (1.0f + __expf(-acc));
        g_xch[((size_t)(b * L_ + l)) * DI_ + d] = __float2half_rn(s);
    }
}

// ---------------- x_dbl via tensor cores, cp.async double-buffered ----------------
__global__ void __launch_bounds__(256) xdbl_kernel() {
    int k = blockIdx.y, b = blockIdx.z;
    int t0 = blockIdx.x * 128;
    int bk = b * K_ + k;

    __shared__ __half As[2][128][40];
    __shared__ __half Bs[2][64][40];

    int tid = threadIdx.x;
    int lane = tid & 31, wid = tid >> 5;
    int wm = wid & 3, wn = wid >> 2;        // 4 x 2 warp grid: warp tile 32m x 32n

    const __half* xcb = g_xch + (size_t)b * L_ * DI_;
    const __half* Wh = g_wX + (size_t)k * 64 * DI_;

    float c[2][4][4];
#pragma unroll
    for (int i = 0; i < 2; ++i)
#pragma unroll
        for (int j = 0; j < 4; ++j)
#pragma unroll
            for (int e = 0; e < 4; ++e) c[i][j][e] = 0.0f;

    int lrow = tid >> 2;
    int lseg = (tid & 3) * 8;
    int lsp0 = map_t(k, t0 + lrow);
    int lsp1 = map_t(k, t0 + 64 + lrow);
    const __half* pa0 = xcb + (size_t)lsp0 * DI_ + lseg;
    const __half* pa1 = xcb + (size_t)lsp1 * DI_ + lseg;
    const __half* pb = Wh + (size_t)(lrow & 63) * DI_ + lseg;  // rows 0..63 used twice? no:
    // Bs has 64 rows: only threads with lrow<64 load; others load second chunk set.
    // Simpler: Bs: 64 rows x 4 segs = 256 cp16 -> one per thread.
    int brow = tid >> 2;           // 0..63
    int bseg = (tid & 3) * 8;
    const __half* pbb = Wh + (size_t)brow * DI_ + bseg;

    {
        cp16(smem_u32(&As[0][lrow][lseg]), pa0);
        cp16(smem_u32(&As[0][64 + lrow][lseg]), pa1);
        if (tid < 256) cp16(smem_u32(&Bs[0][brow][bseg]), pbb);
        CP_COMMIT();
    }

    for (int it = 0; it < DI_ / 32; ++it) {
        if (it + 1 < DI_ / 32) {
            int s = (it + 1) & 1;
            int dk = (it + 1) * 32;
            cp16(smem_u32(&As[s][lrow][lseg]), pa0 + dk);
            cp16(smem_u32(&As[s][64 + lrow][lseg]), pa1 + dk);
            cp16(smem_u32(&Bs[s][brow][bseg]), pbb + dk);
            CP_COMMIT();
            CP_WAIT1();
        } else {
            CP_WAIT0();
        }
        __syncthreads();
        int s = it & 1;
#pragma unroll
        for (int kk = 0; kk < 2; ++kk) {
            uint32_t a[2][4];
#pragma unroll
            for (int mi = 0; mi < 2; ++mi) {
                uint32_t addr = smem_u32(&As[s][wm * 32 + mi * 16 + (lane & 15)]
                                              [kk * 16 + ((lane >> 4) << 3)]);
                ldsm4(a[mi], addr);
            }
            uint32_t bfr[4][2];
#pragma unroll
            for (int nj = 0; nj < 2; ++nj) {
                int n_off = (lane & 7) + ((lane >> 4) << 3);
                int kh = ((lane >> 3) & 1) * 8;
                uint32_t addr = smem_u32(&Bs[s][wn * 32 + nj * 16 + n_off][kk * 16 + kh]);
                uint32_t t4[4];
                ldsm4(t4, addr);
                bfr[2 * nj][0] = t4[0]; bfr[2 * nj][1] = t4[1];
                bfr[2 * nj + 1][0] = t4[2]; bfr[2 * nj + 1][1] = t4[3];
            }
#pragma unroll
            for (int mi = 0; mi < 2; ++mi)
#pragma unroll
                for (int ni = 0; ni < 4; ++ni)
                    mma16816(c[mi][ni], a[mi], bfr[ni]);
        }
        __syncthreads();
    }

    float* outb = g_xdbl + ((size_t)bk * L_ + t0) * 64;
#pragma unroll
    for (int mi = 0; mi < 2; ++mi) {
#pragma unroll
        for (int ni = 0; ni < 4; ++ni) {
            int r0 = wm * 32 + mi * 16 + (lane >> 2);
            int cc = wn * 32 + ni * 8 + ((lane & 3) << 1);
            *(float2*)(outb + (size_t)r0 * 64 + cc) = make_float2(c[mi][ni][0], c[mi][ni][1]);
            *(float2*)(outb + (size_t)(r0 + 8) * 64 + cc) = make_float2(c[mi][ni][2], c[mi][ni][3]);
        }
    }
}

// ---------------- dts[bk,t,d] = softplus( xdbl[bk,t,0:32] . dtw[k,d,:] + dtb[k,d] ) ----
__global__ void __launch_bounds__(256) dts_kernel(const float* __restrict__ dtw,
                                                  const float* __restrict__ dtb) {
    int bk = blockIdx.z;
    int k = bk & 3;
    int t0 = blockIdx.y * 64, d0 = blockIdx.x * 64;
    __shared__ float As[32][68];  // [r][t]
    __shared__ float Ws[32][68];  // [r][d]
    int tid = threadIdx.x;
    int tx = tid & 15, ty = tid >> 4;
#pragma unroll
    for (int it = 0; it < 2; ++it) {
        int t4 = tid + it * 256;
        int row = t4 >> 3;
        int rc = (t4 & 7) << 2;
        float4 va = *(const float4*)(g_xdbl + ((size_t)bk * L_ + t0 + row) * 64 + rc);
        As[rc + 0][row] = va.x; As[rc + 1][row] = va.y;
        As[rc + 2][row] = va.z; As[rc + 3][row] = va.w;
        float4 vw = *(const float4*)(dtw + ((size_t)(k * DI_ + d0 + row)) * R_ + rc);
        Ws[rc + 0][row] = vw.x; Ws[rc + 1][row] = vw.y;
        Ws[rc + 2][row] = vw.z; Ws[rc + 3][row] = vw.w;
    }
    __syncthreads();
    float acc[4][4];
#pragma unroll
    for (int i = 0; i < 4; ++i)
#pragma unroll
        for (int j = 0; j < 4; ++j) acc[i][j] = 0.0f;
#pragma unroll
    for (int r = 0; r < 32; ++r) {
        float4 a = *(const float4*)&As[r][ty * 4];
        float4 w4 = *(const float4*)&Ws[r][tx * 4];
        float av[4] = {a.x, a.y, a.z, a.w};
        float wv[4] = {w4.x, w4.y, w4.z, w4.w};
#pragma unroll
        for (int i = 0; i < 4; ++i)
#pragma unroll
            for (int j = 0; j < 4; ++j)
                acc[i][j] = fmaf(av[i], wv[j], acc[i][j]);
    }
#pragma unroll
    for (int i = 0; i < 4; ++i) {
        float sp[4];
#pragma unroll
        for (int j = 0; j < 4; ++j) {
            int d = d0 + tx * 4 + j;
            float val = acc[i][j] + dtb[k * DI_ + d];
            sp[j] = (val > 20.0f) ? val : log1pf(__expf(val));
        }
        __half* dst = g_dtsh + ((size_t)bk * L_ + t0 + ty * 4 + i) * DI_ + d0 + tx * 4;
        *(__half2*)(dst)     = __floats2half2_rn(sp[0], sp[1]);
        *(__half2*)(dst + 2) = __floats2half2_rn(sp[2], sp[3]);
    }
}

// ---------------- selective scan: smem-staged B/C + prefetched u/dt ----------------
__global__ void __launch_bounds__(256) scan_kernel(const float* __restrict__ A_logs,
                                                   const float* __restrict__ Ds) {
    int b = blockIdx.z, k = blockIdx.y;
    int d = blockIdx.x * 256 + threadIdx.x;
    int bk = b * K_ + k;
    int row = k * DI_ + d;

    float An[N_];
#pragma unroll
    for (int n = 0; n < N_; ++n) An[n] = -__expf(A_logs[(size_t)row * N_ + n]);
    float Dv = Ds[row];
    float h[N_];
#pragma unroll
    for (int n = 0; n < N_; ++n) h[n] = 0.0f;

    const float* xd = g_xdbl + (size_t)bk * L_ * 64;
    const __half* dtp = g_dtsh + (size_t)bk * L_ * DI_ + d;
    __half* ysk = g_ysh + (size_t)bk * L_ * DI_ + d;
    const __half* up = g_xch + (size_t)b * L_ * DI_ + d;

    __shared__ float sbc[64][32];   // [tt][c], c = B(0..15) C(16..31)

    // prefetch u/dt for t = 0, 1
    float ubuf[2], dtbuf[2];
    ubuf[0]  = __half2float(__ldg(up + (size_t)map_t(k, 0) * DI_));
    dtbuf[0] = __half2float(__ldg(dtp));
    ubuf[1]  = __half2float(__ldg(up + (size_t)map_t(k, 1) * DI_));
    dtbuf[1] = __half2float(__ldg(dtp + DI_));

    for (int t0 = 0; t0 < L_; t0 += 64) {
        __syncthreads();
#pragma unroll
        for (int i = 0; i < 8; ++i) {
            int idx = threadIdx.x + i * 256;
            sbc[idx >> 5][idx & 31] = __ldg(xd + (size_t)(t0 + (idx >> 5)) * 64 + 32 + (idx & 31));
        }
        __syncthreads();
#pragma unroll 2
        for (int tt = 0; tt < 64; ++tt) {
            int t = t0 + tt;
            float u  = ubuf[t & 1];
            float dt = dtbuf[t & 1];
            int tn = t + 2;
            if (tn < L_) {
                ubuf[t & 1]  = __half2float(__ldg(up + (size_t)map_t(k, tn) * DI_));
                dtbuf[t & 1] = __half2float(__ldg(dtp + (size_t)tn * DI_));
            }
            float bc[32];
#pragma unroll
            for (int j = 0; j < 8; ++j) {
                float4 v = *(const float4*)&sbc[tt][4 * j];
                bc[4 * j + 0] = v.x; bc[4 * j + 1] = v.y;
                bc[4 * j + 2] = v.z; bc[4 * j + 3] = v.w;
            }
            float du = dt * u;
            float y = Dv * u;
#pragma unroll
            for (int n = 0; n < N_; ++n) {
                float dA = __expf(dt * An[n]);
                h[n] = h[n] * dA + du * bc[n];
                y = fmaf(h[n], bc[16 + n], y);
            }
            ysk[(size_t)map_t(k, t) * DI_] = __float2half_rn(y);
        }
    }
}

// ---------------- combine 4 dirs + out-layernorm + silu(z) gate -> half ----------------
__global__ void __launch_bounds__(256) combine_kernel(const float* __restrict__ onw,
                                                      const float* __restrict__ onb) {
    int bl = blockIdx.x;
    int b = bl >> 10;
    int l = bl & 1023;
    int tid = threadIdx.x;
    int d0 = tid * 4;

    float a0 = 0.f, a1 = 0.f, a2 = 0.f, a3 = 0.f;
#pragma unroll
    for (int k = 0; k < K_; ++k) {
        const __half* p = g_ysh + (((size_t)(b * K_ + k)) * L_ + l) * DI_ + d0;
        __half2 h01 = *(const __half2*)(p);
        __half2 h23 = *(const __half2*)(p + 2);
        float2 f01 = __half22float2(h01);
        float2 f23 = __half22float2(h23);
        a0 += f01.x; a1 += f01.y; a2 += f23.x; a3 += f23.y;
    }
    float s = a0 + a1 + a2 + a3;
    float q = a0 * a0 + a1 * a1 + a2 * a2 + a3 * a3;
#pragma unroll
    for (int o = 16; o; o >>= 1) {
        s += __shfl_xor_sync(0xffffffffu, s, o);
        q += __shfl_xor_sync(0xffffffffu, q, o);
    }
    __shared__ float shs[8], shq[8];
    if ((tid & 31) == 0) { shs[tid >> 5] = s; shq[tid >> 5] = q; }
    __syncthreads();
    float S = 0.f, Q = 0.f;
#pragma unroll
    for (int i = 0; i < 8; ++i) { S += shs[i]; Q += shq[i]; }
    float mu  = S * (1.0f / DI_);
    float var = Q * (1.0f / DI_) - mu * mu;
    float rs  = rsqrtf(var + 1e-5f);

    float4 wv = *(const float4*)(onw + d0);
    float4 bv = *(const float4*)(onb + d0);
    const __half* zp = g_xzh + (size_t)bl * (2 * DI_) + DI_ + d0;
    float2 z01 = __half22float2(*(const __half2*)(zp));
    float2 z23 = __half22float2(*(const __half2*)(zp + 2));

    float ln0 = (a0 - mu) * rs * wv.x + bv.x;
    float ln1 = (a1 - mu) * rs * wv.y + bv.y;
    float ln2 = (a2 - mu) * rs * wv.z + bv.z;
    float ln3 = (a3 - mu) * rs * wv.w + bv.w;
    float o0 = ln0 * (z01.x / (1.0f + __expf(-z01.x)));
    float o1 = ln1 * (z01.y / (1.0f + __expf(-z01.y)));
    float o2 = ln2 * (z23.x / (1.0f + __expf(-z23.x)));
    float o3 = ln3 * (z23.y / (1.0f + __expf(-z23.y)));

    __half* dst = g_yfh + (size_t)bl * DI_ + d0;
    *(__half2*)(dst)     = __floats2half2_rn(o0, o1);
    *(__half2*)(dst + 2) = __floats2half2_rn(o2, o3);
}

// ---------------- launch ----------------
extern "C" void kernel_launch(void* const* d_in, const int* in_sizes, int n_in,
                              void* d_out, int out_size) {
    const float* x          = (const float*)d_in[0];
    const float* norm_w     = (const float*)d_in[1];
    const float* norm_b     = (const float*)d_in[2];
    const float* in_proj_w  = (const float*)d_in[3];
    const float* conv_w     = (const float*)d_in[4];
    const float* conv_b     = (const float*)d_in[5];
    const float* x_proj_w   = (const float*)d_in[6];
    const float* dt_projs_w = (const float*)d_in[7];
    const float* dt_projs_b = (const float*)d_in[8];
    const float* A_logs     = (const float*)d_in[9];
    const float* Ds         = (const float*)d_in[10];
    const float* out_norm_w = (const float*)d_in[11];
    const float* out_norm_b = (const float*)d_in[12];
    const float* out_proj_w = (const float*)d_in[13];
    float* out = (float*)d_out;

    convert_kernel<<<(2 * DI_ * C_) / 256, 256>>>(in_proj_w, out_proj_w, x_proj_w);
    ln_kernel<<<ML_, 128>>>(x, norm_w, norm_b);
    hgemm_nt<0><<<dim3((2 * DI_) / 128, ML_ / 128), 256>>>(nullptr, nullptr);
    conv_kernel<<<dim3(L_, B_), 256>>>(conv_w, conv_b);
    xdbl_kernel<<<dim3(L_ / 128, K_, B_), 256>>>();
    dts_kernel<<<dim3(DI_ / 64, L_ / 64, B_ * K_), 256>>>(dt_projs_w, dt_projs_b);
    scan_kernel<<<dim3(DI_ / 256, K_, B_), 256>>>(A_logs, Ds);
    combine_kernel<<<ML_, 256>>>(out_norm_w, out_norm_b);
    hgemm_nt<1><<<dim3(C_ / 128, ML_ / 128), 256>>>(x, out);
}

// round 6
// speedup vs baseline: 3.0608x; 1.4589x over previous
#include <cuda_runtime.h>
#include <cuda_fp16.h>
#include <math.h>
#include <stdint.h>

// ---------------- problem constants ----------------
#define B_   8
#define H_   32
#define W_   32
#define L_   1024
#define C_   512
#define DI_  1024
#define K_   4
#define N_   16
#define R_   32
#define ML_  (B_ * L_)          // 8192 rows

// ---------------- scratch (device globals) ----------------
__device__ __half g_xnh [(size_t)ML_ * C_];            // layernorm(x)  (half)
__device__ __half g_xzh [(size_t)ML_ * 2 * DI_];       // in_proj out   (half)
__device__ __half g_xch [(size_t)ML_ * DI_];           // conv+silu     (half)
__device__ float  g_xdbl[(size_t)B_ * K_ * L_ * 64];   // (bk, t, c)    fp32
__device__ __half g_dtsh[(size_t)B_ * K_ * L_ * DI_];  // (bk, t, d)    half
__device__ __half g_ysh [(size_t)B_ * K_ * L_ * DI_];  // (bk, l, d)    half
__device__ __half g_yfh [(size_t)ML_ * DI_];           // pre-out_proj  half
__device__ __half g_wA  [2 * DI_ * C_];                // in_proj_w  half
__device__ __half g_wB  [C_ * DI_];                    // out_proj_w half
__device__ __half g_wX  [K_ * 64 * DI_];               // x_proj_w   half

// scan index map: spatial l for direction k at scan step t
__device__ __forceinline__ int map_t(int k, int t) {
    int tt = (k & 2) ? (L_ - 1 - t) : t;
    return (k & 1) ? (((tt & 31) << 5) | (tt >> 5)) : tt;
}

__device__ __forceinline__ uint32_t smem_u32(const void* p) {
    return (uint32_t)__cvta_generic_to_shared(p);
}
__device__ __forceinline__ void ldsm4(uint32_t* r, uint32_t addr) {
    asm volatile("ldmatrix.sync.aligned.m8n8.x4.shared.b16 {%0,%1,%2,%3}, [%4];"
                 : "=r"(r[0]), "=r"(r[1]), "=r"(r[2]), "=r"(r[3]) : "r"(addr));
}
__device__ __forceinline__ void mma16816(float* c, const uint32_t* a, const uint32_t* b) {
    asm volatile("mma.sync.aligned.m16n8k16.row.col.f32.f16.f16.f32 "
                 "{%0,%1,%2,%3}, {%4,%5,%6,%7}, {%8,%9}, {%0,%1,%2,%3};"
                 : "+f"(c[0]), "+f"(c[1]), "+f"(c[2]), "+f"(c[3])
                 : "r"(a[0]), "r"(a[1]), "r"(a[2]), "r"(a[3]), "r"(b[0]), "r"(b[1]));
}
__device__ __forceinline__ void cp16(uint32_t dst, const void* src) {
    asm volatile("cp.async.cg.shared.global [%0], [%1], 16;\n" :: "r"(dst), "l"(src));
}
#define CP_COMMIT() asm volatile("cp.async.commit_group;\n" ::: "memory")
#define CP_WAIT1()  asm volatile("cp.async.wait_group 1;\n" ::: "memory")
#define CP_WAIT0()  asm volatile("cp.async.wait_group 0;\n" ::: "memory")

// ---------------- packed f32x2 helpers (sm_100+) ----------------
typedef unsigned long long u64t;
__device__ __forceinline__ u64t pack2(float lo, float hi) {
    u64t r; asm("mov.b64 %0, {%1, %2};" : "=l"(r) : "f"(lo), "f"(hi)); return r;
}
__device__ __forceinline__ void unpack2(float& lo, float& hi, u64t v) {
    asm("mov.b64 {%0, %1}, %2;" : "=f"(lo), "=f"(hi) : "l"(v));
}
__device__ __forceinline__ u64t mul2(u64t a, u64t b) {
    u64t r; asm("mul.rn.f32x2 %0, %1, %2;" : "=l"(r) : "l"(a), "l"(b)); return r;
}
__device__ __forceinline__ u64t fma2(u64t a, u64t b, u64t c) {
    u64t r; asm("fma.rn.f32x2 %0, %1, %2, %3;" : "=l"(r) : "l"(a), "l"(b), "l"(c)); return r;
}

// ---------------- weight fp32 -> fp16 convert ----------------
__global__ void __launch_bounds__(256) convert_kernel(const float* __restrict__ ipw,
                                                      const float* __restrict__ opw,
                                                      const float* __restrict__ xpw) {
    int i = blockIdx.x * 256 + threadIdx.x;
    if (i < 2 * DI_ * C_) g_wA[i] = __float2half_rn(ipw[i]);
    if (i < C_ * DI_)     g_wB[i] = __float2half_rn(opw[i]);
    if (i < K_ * 64 * DI_) g_wX[i] = __float2half_rn(xpw[i]);
}

// ---------------- input layernorm (row = 512) -> half ----------------
__global__ void __launch_bounds__(128) ln_kernel(const float* __restrict__ x,
                                                 const float* __restrict__ w,
                                                 const float* __restrict__ bb) {
    int bl = blockIdx.x;
    int tid = threadIdx.x;
    const float* xr = x + (size_t)bl * C_;
    float4 v = *(const float4*)(xr + tid * 4);
    float s = v.x + v.y + v.z + v.w;
    float q = v.x * v.x + v.y * v.y + v.z * v.z + v.w * v.w;
#pragma unroll
    for (int o = 16; o; o >>= 1) {
        s += __shfl_xor_sync(0xffffffffu, s, o);
        q += __shfl_xor_sync(0xffffffffu, q, o);
    }
    __shared__ float shs[4], shq[4];
    if ((tid & 31) == 0) { shs[tid >> 5] = s; shq[tid >> 5] = q; }
    __syncthreads();
    float S = shs[0] + shs[1] + shs[2] + shs[3];
    float Q = shq[0] + shq[1] + shq[2] + shq[3];
    float mu  = S * (1.0f / C_);
    float var = Q * (1.0f / C_) - mu * mu;
    float rs  = rsqrtf(var + 1e-5f);
    float4 wv = *(const float4*)(w + tid * 4);
    float4 bv = *(const float4*)(bb + tid * 4);
    float o0 = (v.x - mu) * rs * wv.x + bv.x;
    float o1 = (v.y - mu) * rs * wv.y + bv.y;
    float o2 = (v.z - mu) * rs * wv.z + bv.z;
    float o3 = (v.w - mu) * rs * wv.w + bv.w;
    __half* dst = g_xnh + (size_t)bl * C_ + tid * 4;
    *(__half2*)(dst)     = __floats2half2_rn(o0, o1);
    *(__half2*)(dst + 2) = __floats2half2_rn(o2, o3);
}

// ---------------- tensor-core NT hgemm, cp.async double-buffered ----------------
template <int MODE>
__global__ void __launch_bounds__(256) hgemm_nt(const float* __restrict__ resid,
                                                float* __restrict__ Cout) {
    constexpr int Kd = (MODE == 0) ? C_ : DI_;
    constexpr int Nd = (MODE == 0) ? 2 * DI_ : C_;
    constexpr int NIT = Kd / 32;
    const __half* A = (MODE == 0) ? g_xnh : g_yfh;
    const __half* Wh = (MODE == 0) ? g_wA : g_wB;

    __shared__ __half As[2][128][40];
    __shared__ __half Bs[2][128][40];

    int tid = threadIdx.x;
    int lane = tid & 31, wid = tid >> 5;
    int wm = wid & 1, wn = wid >> 1;
    int m0 = blockIdx.y * 128, n0 = blockIdx.x * 128;

    float c[4][4][4];
#pragma unroll
    for (int i = 0; i < 4; ++i)
#pragma unroll
        for (int j = 0; j < 4; ++j)
#pragma unroll
            for (int e = 0; e < 4; ++e) c[i][j][e] = 0.0f;

    int lrow = tid >> 2;
    int lseg = (tid & 3) * 8;
    const __half* pa0 = A + (size_t)(m0 + lrow) * Kd + lseg;
    const __half* pa1 = A + (size_t)(m0 + 64 + lrow) * Kd + lseg;
    const __half* pb0 = Wh + (size_t)(n0 + lrow) * Kd + lseg;
    const __half* pb1 = Wh + (size_t)(n0 + 64 + lrow) * Kd + lseg;

    {
        cp16(smem_u32(&As[0][lrow][lseg]), pa0);
        cp16(smem_u32(&As[0][64 + lrow][lseg]), pa1);
        cp16(smem_u32(&Bs[0][lrow][lseg]), pb0);
        cp16(smem_u32(&Bs[0][64 + lrow][lseg]), pb1);
        CP_COMMIT();
    }

    for (int it = 0; it < NIT; ++it) {
        if (it + 1 < NIT) {
            int s = (it + 1) & 1;
            int k0 = (it + 1) * 32;
            cp16(smem_u32(&As[s][lrow][lseg]), pa0 + k0);
            cp16(smem_u32(&As[s][64 + lrow][lseg]), pa1 + k0);
            cp16(smem_u32(&Bs[s][lrow][lseg]), pb0 + k0);
            cp16(smem_u32(&Bs[s][64 + lrow][lseg]), pb1 + k0);
            CP_COMMIT();
            CP_WAIT1();
        } else {
            CP_WAIT0();
        }
        __syncthreads();
        int s = it & 1;
#pragma unroll
        for (int kk = 0; kk < 2; ++kk) {
            uint32_t a[4][4];
#pragma unroll
            for (int mi = 0; mi < 4; ++mi) {
                uint32_t addr = smem_u32(&As[s][wm * 64 + mi * 16 + (lane & 15)]
                                              [kk * 16 + ((lane >> 4) << 3)]);
                ldsm4(a[mi], addr);
            }
            uint32_t bfr[4][2];
#pragma unroll
            for (int nj = 0; nj < 2; ++nj) {
                int n_off = (lane & 7) + ((lane >> 4) << 3);
                int kh = ((lane >> 3) & 1) * 8;
                uint32_t addr = smem_u32(&Bs[s][wn * 32 + nj * 16 + n_off][kk * 16 + kh]);
                uint32_t t4[4];
                ldsm4(t4, addr);
                bfr[2 * nj][0] = t4[0]; bfr[2 * nj][1] = t4[1];
                bfr[2 * nj + 1][0] = t4[2]; bfr[2 * nj + 1][1] = t4[3];
            }
#pragma unroll
            for (int mi = 0; mi < 4; ++mi)
#pragma unroll
                for (int ni = 0; ni < 4; ++ni)
                    mma16816(c[mi][ni], a[mi], bfr[ni]);
        }
        __syncthreads();
    }

#pragma unroll
    for (int mi = 0; mi < 4; ++mi) {
#pragma unroll
        for (int ni = 0; ni < 4; ++ni) {
            int r0 = m0 + wm * 64 + mi * 16 + (lane >> 2);
            int cc = n0 + wn * 32 + ni * 8 + ((lane & 3) << 1);
            if (MODE == 0) {
                *(__half2*)(g_xzh + (size_t)r0 * Nd + cc) =
                    __floats2half2_rn(c[mi][ni][0], c[mi][ni][1]);
                *(__half2*)(g_xzh + (size_t)(r0 + 8) * Nd + cc) =
                    __floats2half2_rn(c[mi][ni][2], c[mi][ni][3]);
            } else {
                float2 ra = *(const float2*)(resid + (size_t)r0 * Nd + cc);
                float2 rb = *(const float2*)(resid + (size_t)(r0 + 8) * Nd + cc);
                float2 oa = make_float2(c[mi][ni][0] + ra.x, c[mi][ni][1] + ra.y);
                float2 ob = make_float2(c[mi][ni][2] + rb.x, c[mi][ni][3] + rb.y);
                *(float2*)(Cout + (size_t)r0 * Nd + cc) = oa;
                *(float2*)(Cout + (size_t)(r0 + 8) * Nd + cc) = ob;
            }
        }
    }
}

// ---------------- depthwise 3x3 conv + bias + silu (half in/out, vectorized) ----
__global__ void __launch_bounds__(512) conv_kernel(const float* __restrict__ cw,
                                                   const float* __restrict__ cb) {
    int l = blockIdx.x, b = blockIdx.y;
    int h = l >> 5, w = l & 31;
    int d = threadIdx.x * 2;

    // hoist neighbor offsets + validity once
    const __half* base = g_xzh + ((size_t)(b * L_)) * (2 * DI_) + d;
    float a0 = cb[d], a1 = cb[d + 1];
    const float* w0p = cw + d * 9;
    const float* w1p = cw + d * 9 + 9;

#pragma unroll
    for (int dy = -1; dy <= 1; ++dy) {
        int hh = h + dy;
        if ((unsigned)hh >= 32u) continue;
        const __half* rowp = base + (size_t)(hh << 5) * (2 * DI_);
        int wi = (dy + 1) * 3;
#pragma unroll
        for (int dx = -1; dx <= 1; ++dx) {
            int ww = w + dx;
            if ((unsigned)ww >= 32u) continue;
            float2 xf = __half22float2(*(const __half2*)(rowp + (size_t)ww * (2 * DI_)));
            float w0 = __ldg(w0p + wi + dx + 1);
            float w1 = __ldg(w1p + wi + dx + 1);
            a0 = fmaf(xf.x, w0, a0);
            a1 = fmaf(xf.y, w1, a1);
        }
    }
    float s0 = a0 / (1.0f + __expf(-a0));
    float s1 = a1 / (1.0f + __expf(-a1));
    *(__half2*)(g_xch + ((size_t)(b * L_ + l)) * DI_ + d) = __floats2half2_rn(s0, s1);
}

// ---------------- x_dbl via tensor cores, cp.async double-buffered ----------------
__global__ void __launch_bounds__(256) xdbl_kernel() {
    int k = blockIdx.y, b = blockIdx.z;
    int t0 = blockIdx.x * 128;
    int bk = b * K_ + k;

    __shared__ __half As[2][128][40];
    __shared__ __half Bs[2][64][40];

    int tid = threadIdx.x;
    int lane = tid & 31, wid = tid >> 5;
    int wm = wid & 3, wn = wid >> 2;

    const __half* xcb = g_xch + (size_t)b * L_ * DI_;
    const __half* Wh = g_wX + (size_t)k * 64 * DI_;

    float c[2][4][4];
#pragma unroll
    for (int i = 0; i < 2; ++i)
#pragma unroll
        for (int j = 0; j < 4; ++j)
#pragma unroll
            for (int e = 0; e < 4; ++e) c[i][j][e] = 0.0f;

    int lrow = tid >> 2;
    int lseg = (tid & 3) * 8;
    int lsp0 = map_t(k, t0 + lrow);
    int lsp1 = map_t(k, t0 + 64 + lrow);
    const __half* pa0 = xcb + (size_t)lsp0 * DI_ + lseg;
    const __half* pa1 = xcb + (size_t)lsp1 * DI_ + lseg;
    int brow = tid >> 2;
    int bseg = (tid & 3) * 8;
    const __half* pbb = Wh + (size_t)brow * DI_ + bseg;

    {
        cp16(smem_u32(&As[0][lrow][lseg]), pa0);
        cp16(smem_u32(&As[0][64 + lrow][lseg]), pa1);
        cp16(smem_u32(&Bs[0][brow][bseg]), pbb);
        CP_COMMIT();
    }

    for (int it = 0; it < DI_ / 32; ++it) {
        if (it + 1 < DI_ / 32) {
            int s = (it + 1) & 1;
            int dk = (it + 1) * 32;
            cp16(smem_u32(&As[s][lrow][lseg]), pa0 + dk);
            cp16(smem_u32(&As[s][64 + lrow][lseg]), pa1 + dk);
            cp16(smem_u32(&Bs[s][brow][bseg]), pbb + dk);
            CP_COMMIT();
            CP_WAIT1();
        } else {
            CP_WAIT0();
        }
        __syncthreads();
        int s = it & 1;
#pragma unroll
        for (int kk = 0; kk < 2; ++kk) {
            uint32_t a[2][4];
#pragma unroll
            for (int mi = 0; mi < 2; ++mi) {
                uint32_t addr = smem_u32(&As[s][wm * 32 + mi * 16 + (lane & 15)]
                                              [kk * 16 + ((lane >> 4) << 3)]);
                ldsm4(a[mi], addr);
            }
            uint32_t bfr[4][2];
#pragma unroll
            for (int nj = 0; nj < 2; ++nj) {
                int n_off = (lane & 7) + ((lane >> 4) << 3);
                int kh = ((lane >> 3) & 1) * 8;
                uint32_t addr = smem_u32(&Bs[s][wn * 32 + nj * 16 + n_off][kk * 16 + kh]);
                uint32_t t4[4];
                ldsm4(t4, addr);
                bfr[2 * nj][0] = t4[0]; bfr[2 * nj][1] = t4[1];
                bfr[2 * nj + 1][0] = t4[2]; bfr[2 * nj + 1][1] = t4[3];
            }
#pragma unroll
            for (int mi = 0; mi < 2; ++mi)
#pragma unroll
                for (int ni = 0; ni < 4; ++ni)
                    mma16816(c[mi][ni], a[mi], bfr[ni]);
        }
        __syncthreads();
    }

    float* outb = g_xdbl + ((size_t)bk * L_ + t0) * 64;
#pragma unroll
    for (int mi = 0; mi < 2; ++mi) {
#pragma unroll
        for (int ni = 0; ni < 4; ++ni) {
            int r0 = wm * 32 + mi * 16 + (lane >> 2);
            int cc = wn * 32 + ni * 8 + ((lane & 3) << 1);
            *(float2*)(outb + (size_t)r0 * 64 + cc) = make_float2(c[mi][ni][0], c[mi][ni][1]);
            *(float2*)(outb + (size_t)(r0 + 8) * 64 + cc) = make_float2(c[mi][ni][2], c[mi][ni][3]);
        }
    }
}

// ---------------- dts[bk,t,d] = softplus( xdbl[bk,t,0:32] . dtw[k,d,:] + dtb[k,d] ) ----
__global__ void __launch_bounds__(256) dts_kernel(const float* __restrict__ dtw,
                                                  const float* __restrict__ dtb) {
    int bk = blockIdx.z;
    int k = bk & 3;
    int t0 = blockIdx.y * 64, d0 = blockIdx.x * 64;
    __shared__ float As[32][68];
    __shared__ float Ws[32][68];
    int tid = threadIdx.x;
    int tx = tid & 15, ty = tid >> 4;
#pragma unroll
    for (int it = 0; it < 2; ++it) {
        int t4 = tid + it * 256;
        int row = t4 >> 3;
        int rc = (t4 & 7) << 2;
        float4 va = *(const float4*)(g_xdbl + ((size_t)bk * L_ + t0 + row) * 64 + rc);
        As[rc + 0][row] = va.x; As[rc + 1][row] = va.y;
        As[rc + 2][row] = va.z; As[rc + 3][row] = va.w;
        float4 vw = *(const float4*)(dtw + ((size_t)(k * DI_ + d0 + row)) * R_ + rc);
        Ws[rc + 0][row] = vw.x; Ws[rc + 1][row] = vw.y;
        Ws[rc + 2][row] = vw.z; Ws[rc + 3][row] = vw.w;
    }
    __syncthreads();
    float acc[4][4];
#pragma unroll
    for (int i = 0; i < 4; ++i)
#pragma unroll
        for (int j = 0; j < 4; ++j) acc[i][j] = 0.0f;
#pragma unroll
    for (int r = 0; r < 32; ++r) {
        float4 a = *(const float4*)&As[r][ty * 4];
        float4 w4 = *(const float4*)&Ws[r][tx * 4];
        float av[4] = {a.x, a.y, a.z, a.w};
        float wv[4] = {w4.x, w4.y, w4.z, w4.w};
#pragma unroll
        for (int i = 0; i < 4; ++i)
#pragma unroll
            for (int j = 0; j < 4; ++j)
                acc[i][j] = fmaf(av[i], wv[j], acc[i][j]);
    }
#pragma unroll
    for (int i = 0; i < 4; ++i) {
        float sp[4];
#pragma unroll
        for (int j = 0; j < 4; ++j) {
            int d = d0 + tx * 4 + j;
            float val = acc[i][j] + dtb[k * DI_ + d];
            sp[j] = (val > 20.0f) ? val : log1pf(__expf(val));
        }
        __half* dst = g_dtsh + ((size_t)bk * L_ + t0 + ty * 4 + i) * DI_ + d0 + tx * 4;
        *(__half2*)(dst)     = __floats2half2_rn(sp[0], sp[1]);
        *(__half2*)(dst + 2) = __floats2half2_rn(sp[2], sp[3]);
    }
}

// ---------------- selective scan: packed f32x2 + integer-A fast path ----------------
// thread = (b, k, d); 128 threads/block, 256 blocks.
__global__ void __launch_bounds__(128) scan_kernel(const float* __restrict__ A_logs,
                                                   const float* __restrict__ Ds) {
    int b = blockIdx.z, k = blockIdx.y;
    int d = blockIdx.x * 128 + threadIdx.x;
    int bk = b * K_ + k;
    int row = k * DI_ + d;

    float An[N_];
#pragma unroll
    for (int n = 0; n < N_; ++n) An[n] = -__expf(A_logs[(size_t)row * N_ + n]);
    float A1 = An[0];
    // fast path iff An[n] == (n+1)*An[0] (then dA_n = exp(dt*A1)^(n+1))
    bool fast = true;
#pragma unroll
    for (int n = 1; n < N_; ++n)
        fast = fast && (fabsf(An[n] - (float)(n + 1) * A1) <= 1e-4f * fabsf(An[n]));

    float Dv = Ds[row];
    u64t h2[8];
#pragma unroll
    for (int j = 0; j < 8; ++j) h2[j] = 0ull;

    const float* xd = g_xdbl + (size_t)bk * L_ * 64;
    const __half* dtp = g_dtsh + (size_t)bk * L_ * DI_ + d;
    __half* ysk = g_ysh + (size_t)bk * L_ * DI_ + d;
    const __half* up = g_xch + (size_t)b * L_ * DI_ + d;

    __shared__ u64t sbc[64][16];   // [tt][pair]: pairs 0..7 = B, 8..15 = C

    float ubuf[2], dtbuf[2];
    ubuf[0]  = __half2float(__ldg(up + (size_t)map_t(k, 0) * DI_));
    dtbuf[0] = __half2float(__ldg(dtp));
    ubuf[1]  = __half2float(__ldg(up + (size_t)map_t(k, 1) * DI_));
    dtbuf[1] = __half2float(__ldg(dtp + DI_));

    for (int t0 = 0; t0 < L_; t0 += 64) {
        __syncthreads();
#pragma unroll
        for (int i = 0; i < 8; ++i) {
            int p = threadIdx.x + i * 128;       // 0..1023
            int tt = p >> 4, c2 = p & 15;
            float2 v = *(const float2*)(xd + (size_t)(t0 + tt) * 64 + 32 + 2 * c2);
            sbc[tt][c2] = pack2(v.x, v.y);
        }
        __syncthreads();

        if (fast) {
#pragma unroll 2
            for (int tt = 0; tt < 64; ++tt) {
                int t = t0 + tt;
                float u  = ubuf[t & 1];
                float dt = dtbuf[t & 1];
                int tn = t + 2;
                if (tn < L_) {
                    ubuf[t & 1]  = __half2float(__ldg(up + (size_t)map_t(k, tn) * DI_));
                    dtbuf[t & 1] = __half2float(__ldg(dtp + (size_t)tn * DI_));
                }
                float du = dt * u;
                u64t du2 = pack2(du, du);
                float e1 = __expf(dt * A1);
                float e2s = e1 * e1;
                u64t dAj = pack2(e1, e2s);
                u64t E2 = pack2(e2s, e2s);
                u64t yacc = pack2(Dv * u, 0.0f);
                const ulonglong2* pr = (const ulonglong2*)&sbc[tt][0];
                u64t bc[16];
#pragma unroll
                for (int jj = 0; jj < 8; ++jj) {
                    ulonglong2 q = pr[jj];
                    bc[2 * jj] = q.x; bc[2 * jj + 1] = q.y;
                }
#pragma unroll
                for (int j = 0; j < 8; ++j) {
                    u64t tmp = mul2(du2, bc[j]);
                    h2[j] = fma2(h2[j], dAj, tmp);
                    yacc = fma2(h2[j], bc[8 + j], yacc);
                    if (j < 7) dAj = mul2(dAj, E2);
                }
                float ylo, yhi;
                unpack2(ylo, yhi, yacc);
                ysk[(size_t)map_t(k, t) * DI_] = __float2half_rn(ylo + yhi);
            }
        } else {
#pragma unroll 2
            for (int tt = 0; tt < 64; ++tt) {
                int t = t0 + tt;
                float u  = ubuf[t & 1];
                float dt = dtbuf[t & 1];
                int tn = t + 2;
                if (tn < L_) {
                    ubuf[t & 1]  = __half2float(__ldg(up + (size_t)map_t(k, tn) * DI_));
                    dtbuf[t & 1] = __half2float(__ldg(dtp + (size_t)tn * DI_));
                }
                float du = dt * u;
                u64t du2 = pack2(du, du);
                u64t yacc = pack2(Dv * u, 0.0f);
                const ulonglong2* pr = (const ulonglong2*)&sbc[tt][0];
                u64t bc[16];
#pragma unroll
                for (int jj = 0; jj < 8; ++jj) {
                    ulonglong2 q = pr[jj];
                    bc[2 * jj] = q.x; bc[2 * jj + 1] = q.y;
                }
#pragma unroll
                for (int j = 0; j < 8; ++j) {
                    u64t dA2 = pack2(__expf(dt * An[2 * j]), __expf(dt * An[2 * j + 1]));
                    u64t tmp = mul2(du2, bc[j]);
                    h2[j] = fma2(h2[j], dA2, tmp);
                    yacc = fma2(h2[j], bc[8 + j], yacc);
                }
                float ylo, yhi;
                unpack2(ylo, yhi, yacc);
                ysk[(size_t)map_t(k, t) * DI_] = __float2half_rn(ylo + yhi);
            }
        }
    }
}

// ---------------- combine 4 dirs + out-layernorm + silu(z) gate -> half ----------------
__global__ void __launch_bounds__(256) combine_kernel(const float* __restrict__ onw,
                                                      const float* __restrict__ onb) {
    int bl = blockIdx.x;
    int b = bl >> 10;
    int l = bl & 1023;
    int tid = threadIdx.x;
    int d0 = tid * 4;

    float a0 = 0.f, a1 = 0.f, a2 = 0.f, a3 = 0.f;
#pragma unroll
    for (int k = 0; k < K_; ++k) {
        const __half* p = g_ysh + (((size_t)(b * K_ + k)) * L_ + l) * DI_ + d0;
        __half2 h01 = *(const __half2*)(p);
        __half2 h23 = *(const __half2*)(p + 2);
        float2 f01 = __half22float2(h01);
        float2 f23 = __half22float2(h23);
        a0 += f01.x; a1 += f01.y; a2 += f23.x; a3 += f23.y;
    }
    float s = a0 + a1 + a2 + a3;
    float q = a0 * a0 + a1 * a1 + a2 * a2 + a3 * a3;
#pragma unroll
    for (int o = 16; o; o >>= 1) {
        s += __shfl_xor_sync(0xffffffffu, s, o);
        q += __shfl_xor_sync(0xffffffffu, q, o);
    }
    __shared__ float shs[8], shq[8];
    if ((tid & 31) == 0) { shs[tid >> 5] = s; shq[tid >> 5] = q; }
    __syncthreads();
    float S = 0.f, Q = 0.f;
#pragma unroll
    for (int i = 0; i < 8; ++i) { S += shs[i]; Q += shq[i]; }
    float mu  = S * (1.0f / DI_);
    float var = Q * (1.0f / DI_) - mu * mu;
    float rs  = rsqrtf(var + 1e-5f);

    float4 wv = *(const float4*)(onw + d0);
    float4 bv = *(const float4*)(onb + d0);
    const __half* zp = g_xzh + (size_t)bl * (2 * DI_) + DI_ + d0;
    float2 z01 = __half22float2(*(const __half2*)(zp));
    float2 z23 = __half22float2(*(const __half2*)(zp + 2));

    float ln0 = (a0 - mu) * rs * wv.x + bv.x;
    float ln1 = (a1 - mu) * rs * wv.y + bv.y;
    float ln2 = (a2 - mu) * rs * wv.z + bv.z;
    float ln3 = (a3 - mu) * rs * wv.w + bv.w;
    float o0 = ln0 * (z01.x / (1.0f + __expf(-z01.x)));
    float o1 = ln1 * (z01.y / (1.0f + __expf(-z01.y)));
    float o2 = ln2 * (z23.x / (1.0f + __expf(-z23.x)));
    float o3 = ln3 * (z23.y / (1.0f + __expf(-z23.y)));

    __half* dst = g_yfh + (size_t)bl * DI_ + d0;
    *(__half2*)(dst)     = __floats2half2_rn(o0, o1);
    *(__half2*)(dst + 2) = __floats2half2_rn(o2, o3);
}

// ---------------- launch ----------------
extern "C" void kernel_launch(void* const* d_in, const int* in_sizes, int n_in,
                              void* d_out, int out_size) {
    const float* x          = (const float*)d_in[0];
    const float* norm_w     = (const float*)d_in[1];
    const float* norm_b     = (const float*)d_in[2];
    const float* in_proj_w  = (const float*)d_in[3];
    const float* conv_w     = (const float*)d_in[4];
    const float* conv_b     = (const float*)d_in[5];
    const float* x_proj_w   = (const float*)d_in[6];
    const float* dt_projs_w = (const float*)d_in[7];
    const float* dt_projs_b = (const float*)d_in[8];
    const float* A_logs     = (const float*)d_in[9];
    const float* Ds         = (const float*)d_in[10];
    const float* out_norm_w = (const float*)d_in[11];
    const float* out_norm_b = (const float*)d_in[12];
    const float* out_proj_w = (const float*)d_in[13];
    float* out = (float*)d_out;

    convert_kernel<<<(2 * DI_ * C_) / 256, 256>>>(in_proj_w, out_proj_w, x_proj_w);
    ln_kernel<<<ML_, 128>>>(x, norm_w, norm_b);
    hgemm_nt<0><<<dim3((2 * DI_) / 128, ML_ / 128), 256>>>(nullptr, nullptr);
    conv_kernel<<<dim3(L_, B_), 512>>>(conv_w, conv_b);
    xdbl_kernel<<<dim3(L_ / 128, K_, B_), 256>>>();
    dts_kernel<<<dim3(DI_ / 64, L_ / 64, B_ * K_), 256>>>(dt_projs_w, dt_projs_b);
    scan_kernel<<<dim3(DI_ / 128, K_, B_), 128>>>(A_logs, Ds);
    combine_kernel<<<ML_, 256>>>(out_norm_w, out_norm_b);
    hgemm_nt<1><<<dim3(C_ / 128, ML_ / 128), 256>>>(x, out);
}